// round 2
// baseline (speedup 1.0000x reference)
#include <cuda_runtime.h>
#include <math.h>

#define BB   64
#define SS   2048
#define DD   1024
#define HH   300
#define OO   2
#define SCH  16                 // s-chunks for the big reduction
#define SPC  (SS / SCH)         // 128 s per chunk
#define D4   (DD / 4)           // 256 float4 per row

// Scratch (allocation-free rule: __device__ globals)
__device__ int   g_end[BB];
__device__ float g_partial[BB][SCH][DD];
__device__ float g_euph[BB][DD];
__device__ float g_hidden[BB][HH];

// ---------------------------------------------------------------------------
// 1) first index where input_ids[b, s] == 1; fallback = B (reference quirk:
//    `except: end_ind = input_ids.shape[0]` where shape[0] is the batch dim).
//    NOTE: JAX with x64 disabled emits int32 despite dtype=jnp.int64.
// ---------------------------------------------------------------------------
__global__ void k_end(const int* __restrict__ ids) {
    int b = blockIdx.x;
    __shared__ int m;
    if (threadIdx.x == 0) m = 0x7fffffff;
    __syncthreads();
    const int* row = ids + b * SS;
    for (int s = threadIdx.x; s < SS; s += blockDim.x)
        if (row[s] == 1) atomicMin(&m, s);
    __syncthreads();
    if (threadIdx.x == 0) g_end[b] = (m == 0x7fffffff) ? BB : m;
}

// ---------------------------------------------------------------------------
// 2) big masked segment-sum: partial[b][c][d] = sum over s in chunk c, s<end,
//    mask!=0 of inputs[b][s][d]*mask[b][s].  256 threads, thread t owns the
//    float4 at d = 4t. Mask staged in smem; skip (uniform branch) saves DRAM.
// ---------------------------------------------------------------------------
__global__ __launch_bounds__(256) void k_reduce(const float* __restrict__ x,
                                                const float* __restrict__ mask) {
    int b = blockIdx.x;
    int c = blockIdx.y;
    int t = threadIdx.x;
    int end = g_end[b];
    int s0  = c * SPC;

    __shared__ float sm[SPC];
    {
        // stage mask for this chunk, folding the s<end validity in
        int i = t;                    // SPC=128 < 256: first 128 threads load
        if (i < SPC) {
            int s = s0 + i;
            sm[i] = (s < end) ? mask[b * SS + s] : 0.0f;
        }
    }
    __syncthreads();

    const float4* xp = (const float4*)(x + (long long)b * SS * DD) + t;

    float4 acc = make_float4(0.f, 0.f, 0.f, 0.f);
#pragma unroll 4
    for (int i = 0; i < SPC; i++) {
        float m = sm[i];
        if (m != 0.0f) {
            float4 v = xp[(long long)(s0 + i) * D4];
            acc.x += v.x * m;
            acc.y += v.y * m;
            acc.z += v.z * m;
            acc.w += v.w * m;
        }
    }
    ((float4*)g_partial[b][c])[t] = acc;
}

// ---------------------------------------------------------------------------
// 3) fold the SCH partials and divide by end:  euph[b][d]
// ---------------------------------------------------------------------------
__global__ __launch_bounds__(256) void k_combine() {
    int b = blockIdx.x;
    int t = threadIdx.x;
    float inv = 1.0f / (float)g_end[b];
    float4 acc = make_float4(0.f, 0.f, 0.f, 0.f);
#pragma unroll
    for (int c = 0; c < SCH; c++) {
        float4 v = ((const float4*)g_partial[b][c])[t];
        acc.x += v.x; acc.y += v.y; acc.z += v.z; acc.w += v.w;
    }
    acc.x *= inv; acc.y *= inv; acc.z *= inv; acc.w *= inv;
    ((float4*)g_euph[b])[t] = acc;
}

// ---------------------------------------------------------------------------
// 4) hidden = tanh(euph @ W1^T + b1).  Grid (B, H/4), 4 warps/block, one warp
//    per h. Dot of length 1024 via lane-strided accumulate + shfl reduce.
// ---------------------------------------------------------------------------
__global__ __launch_bounds__(128) void k_hidden(const float* __restrict__ W1,
                                                const float* __restrict__ b1) {
    int b    = blockIdx.x;
    int warp = threadIdx.x >> 5;
    int lane = threadIdx.x & 31;
    int h    = blockIdx.y * 4 + warp;        // H = 300 = 75 * 4, always valid

    const float* e = g_euph[b];
    const float* w = W1 + (long long)h * DD;
    float s = 0.f;
#pragma unroll 8
    for (int k = lane; k < DD; k += 32)
        s += e[k] * w[k];
#pragma unroll
    for (int off = 16; off > 0; off >>= 1)
        s += __shfl_xor_sync(0xffffffffu, s, off);
    if (lane == 0)
        g_hidden[b][h] = tanhf(s + b1[h]);
}

// ---------------------------------------------------------------------------
// 5) out = hidden @ W2^T + b2.  Grid B, 2 warps/block, one warp per output.
// ---------------------------------------------------------------------------
__global__ __launch_bounds__(64) void k_out(const float* __restrict__ W2,
                                            const float* __restrict__ b2,
                                            float* __restrict__ out) {
    int b    = blockIdx.x;
    int warp = threadIdx.x >> 5;             // 0..1
    int lane = threadIdx.x & 31;

    const float* hid = g_hidden[b];
    const float* w   = W2 + warp * HH;
    float s = 0.f;
    for (int k = lane; k < HH; k += 32)
        s += hid[k] * w[k];
#pragma unroll
    for (int off = 16; off > 0; off >>= 1)
        s += __shfl_xor_sync(0xffffffffu, s, off);
    if (lane == 0)
        out[b * OO + warp] = s + b2[warp];
}

// ---------------------------------------------------------------------------
extern "C" void kernel_launch(void* const* d_in, const int* in_sizes, int n_in,
                              void* d_out, int out_size) {
    const float* x    = (const float*)d_in[0];       // [B,S,D] f32
    const int*   ids  = (const int*)d_in[1];         // [B,S]   i32 (JAX x64 off)
    const float* mask = (const float*)d_in[2];       // [B,S,1] f32
    const float* W1   = (const float*)d_in[3];       // [H,D]
    const float* b1   = (const float*)d_in[4];       // [H]
    const float* W2   = (const float*)d_in[5];       // [OUT,H]
    const float* b2   = (const float*)d_in[6];       // [OUT]
    float*       out  = (float*)d_out;               // [B,OUT]

    k_end    <<<BB, 256>>>(ids);
    k_reduce <<<dim3(BB, SCH), 256>>>(x, mask);
    k_combine<<<BB, 256>>>();
    k_hidden <<<dim3(BB, HH / 4), 128>>>(W1, b1);
    k_out    <<<BB, 64>>>(W2, b2, out);
}